// round 14
// baseline (speedup 1.0000x reference)
#include <cuda_runtime.h>
#include <math.h>

#define BATCH 4
#define SEQ   4096
#define EMB   512
#define HD    64
#define NSPLIT 7

__device__ float g_q[BATCH * SEQ * HD];
__device__ float g_k[BATCH * SEQ * HD];
__device__ float g_v[BATCH * SEQ * HD];
__device__ float g_part[NSPLIT * BATCH * SEQ * HD];   // unnormalized O partials
__device__ float g_lsum[NSPLIT * BATCH * SEQ];        // exp-sum partials

// ---------------------------------------------------------------------------
__device__ __forceinline__ unsigned f2tf(float x) {
    unsigned r;
    asm("cvt.rna.tf32.f32 %0, %1;" : "=r"(r) : "f"(x));
    return r;
}
__device__ __forceinline__ float ex2(float x) {
    float r;
    asm("ex2.approx.ftz.f32 %0, %1;" : "=f"(r) : "f"(x));
    return r;
}

__device__ __forceinline__ void mma_tf32(float c[4],
                                         unsigned a0, unsigned a1,
                                         unsigned a2, unsigned a3,
                                         unsigned b0, unsigned b1) {
    asm volatile(
        "mma.sync.aligned.m16n8k8.row.col.f32.tf32.tf32.f32 "
        "{%0,%1,%2,%3}, {%4,%5,%6,%7}, {%8,%9}, {%0,%1,%2,%3};"
        : "+f"(c[0]), "+f"(c[1]), "+f"(c[2]), "+f"(c[3])
        : "r"(a0), "r"(a1), "r"(a2), "r"(a3), "r"(b0), "r"(b1));
}

#define CP_COMMIT() asm volatile("cp.async.commit_group;" ::: "memory")
#define CP_WAIT1()  asm volatile("cp.async.wait_group 1;" ::: "memory")

// ---------------------------------------------------------------------------
// tf32 projection (R10 version — proven plateau): CTA = 128 thr / 4 warps,
// m32 warp tiles over a 128-row X tile, single-buffered, convert-at-STS.
// ---------------------------------------------------------------------------
#define PPX 68
#define PROJ_SMEM_FLOATS (128 * PPX + 64 * PPX)
#define PROJ_SMEM_BYTES  (PROJ_SMEM_FLOATS * 4)
#define PNCHUNK (EMB / 64)   // 8

__global__ __launch_bounds__(128, 3) void proj_mma_kernel(
    const float* __restrict__ x,
    const float* __restrict__ WQ,
    const float* __restrict__ WK,
    const float* __restrict__ WV)
{
    extern __shared__ float psm[];
    float* Xs = psm;                // 128 x PPX (tf32 bits)
    float* Ws = psm + 128 * PPX;    // 64 x PPX (tf32 bits)

    const float* W;
    float* out;
    if (blockIdx.y == 0)      { W = WQ; out = g_q; }
    else if (blockIdx.y == 1) { W = WK; out = g_k; }
    else                      { W = WV; out = g_v; }

    const int tid  = threadIdx.x;
    const int lane = tid & 31;
    const int warp = tid >> 5;
    const int g    = lane >> 2;
    const int tq   = lane & 3;
    const int bm   = blockIdx.x * 128;
    const int rw   = 32 * warp;

    const unsigned* Xu = reinterpret_cast<const unsigned*>(Xs);
    const unsigned* Wu = reinterpret_cast<const unsigned*>(Ws);

    float acc[2][8][4];
    #pragma unroll
    for (int h = 0; h < 2; h++)
        #pragma unroll
        for (int n = 0; n < 8; n++)
            #pragma unroll
            for (int j = 0; j < 4; j++) acc[h][n][j] = 0.0f;

    for (int c = 0; c < PNCHUNK; c++) {
        const int k0 = c * 64;
        __syncthreads();
        #pragma unroll
        for (int i = 0; i < 16; i++) {
            int f = tid + 128 * i;
            int row = f >> 4, c4 = f & 15;
            float4 v = *reinterpret_cast<const float4*>(
                &x[(size_t)(bm + row) * EMB + k0 + c4 * 4]);
            uint4 t = { f2tf(v.x), f2tf(v.y), f2tf(v.z), f2tf(v.w) };
            *reinterpret_cast<uint4*>(&Xs[row * PPX + c4 * 4]) = t;
        }
        #pragma unroll
        for (int i = 0; i < 8; i++) {
            int f = tid + 128 * i;
            int row = f >> 4, c4 = f & 15;
            float4 v = *reinterpret_cast<const float4*>(
                &W[(size_t)row * EMB + k0 + c4 * 4]);
            uint4 t = { f2tf(v.x), f2tf(v.y), f2tf(v.z), f2tf(v.w) };
            *reinterpret_cast<uint4*>(&Ws[row * PPX + c4 * 4]) = t;
        }
        __syncthreads();

        #pragma unroll
        for (int kc = 0; kc < 8; kc++) {
            unsigned xa[2][4];
            #pragma unroll
            for (int h = 0; h < 2; h++) {
                int ra = rw + 16 * h + g;
                xa[h][0] = Xu[(ra)     * PPX + 8 * kc + tq];
                xa[h][1] = Xu[(ra + 8) * PPX + 8 * kc + tq];
                xa[h][2] = Xu[(ra)     * PPX + 8 * kc + tq + 4];
                xa[h][3] = Xu[(ra + 8) * PPX + 8 * kc + tq + 4];
            }
            #pragma unroll
            for (int n = 0; n < 8; n++) {
                unsigned b0 = Wu[(8 * n + g) * PPX + 8 * kc + tq];
                unsigned b1 = Wu[(8 * n + g) * PPX + 8 * kc + tq + 4];
                mma_tf32(acc[0][n], xa[0][0], xa[0][1], xa[0][2], xa[0][3], b0, b1);
                mma_tf32(acc[1][n], xa[1][0], xa[1][1], xa[1][2], xa[1][3], b0, b1);
            }
        }
    }

    #pragma unroll
    for (int h = 0; h < 2; h++) {
        int ra = rw + 16 * h + g;
        float* o0 = out + (size_t)(bm + ra)     * HD;
        float* o1 = out + (size_t)(bm + ra + 8) * HD;
        #pragma unroll
        for (int n = 0; n < 8; n++) {
            int cc = 8 * n + 2 * tq;
            float2 w0 = { __uint_as_float(f2tf(acc[h][n][0])),
                          __uint_as_float(f2tf(acc[h][n][1])) };
            float2 w1 = { __uint_as_float(f2tf(acc[h][n][2])),
                          __uint_as_float(f2tf(acc[h][n][3])) };
            *reinterpret_cast<float2*>(&o0[cc]) = w0;
            *reinterpret_cast<float2*>(&o1[cc]) = w1;
        }
    }
}

// ---------------------------------------------------------------------------
// Attention: tf32 mma, m32 warp tile, split-KV NSPLIT=7, cp.async
// double-buffered K/V, shuffle-free S->P (sigma absorbed into V rows).
// NEW: S-mma accumulators split into even/odd-kc partials -> 4 independent
// tensor-pipe chains of depth 4 (was 2 chains of depth 8).
// ---------------------------------------------------------------------------
#define PK   68
#define PV   68
#define KBUF (64 * PK)
#define VBUF (64 * PV)
#define ATTN_SMEM_BYTES ((2 * KBUF + 2 * VBUF) * 4)

__device__ __forceinline__ void attn_load_async(float* Kd, float* Vd,
                                                const float* kg, const float* vg,
                                                int tid) {
    unsigned ka = (unsigned)__cvta_generic_to_shared(Kd);
    unsigned va = (unsigned)__cvta_generic_to_shared(Vd);
    #pragma unroll
    for (int i = 0; i < 8; i++) {
        int f = tid + 128 * i;           // 1024 float4 = 64 rows x 16
        int row = f >> 4, c4 = f & 15;
        asm volatile("cp.async.cg.shared.global [%0], [%1], 16;" ::
            "r"(ka + (unsigned)((row * PK + c4 * 4) * 4)),
            "l"(kg + row * HD + c4 * 4) : "memory");
        asm volatile("cp.async.cg.shared.global [%0], [%1], 16;" ::
            "r"(va + (unsigned)((row * PV + c4 * 4) * 4)),
            "l"(vg + row * HD + c4 * 4) : "memory");
    }
}

__global__ __launch_bounds__(128) void attn_mma_kernel()
{
    extern __shared__ float sm[];
    float* Kb[2] = { sm, sm + KBUF };
    float* Vb[2] = { sm + 2 * KBUF, sm + 2 * KBUF + VBUF };

    const int tid  = threadIdx.x;
    const int lane = tid & 31;
    const int warp = tid >> 5;
    const int g    = lane >> 2;
    const int tq   = lane & 3;
    const int b    = blockIdx.y;
    const int q0   = blockIdx.x * 128;
    const int z    = blockIdx.z;
    const int t_begin = (64 * z) / NSPLIT;
    const int t_end   = (64 * (z + 1)) / NSPLIT;
    const int nt      = t_end - t_begin;

    const float* qg  = g_q + ((size_t)b * SEQ + q0) * HD;
    const float* kgb = g_k + ((size_t)b * SEQ + (size_t)t_begin * 64) * HD;
    const float* vgb = g_v + ((size_t)b * SEQ + (size_t)t_begin * 64) * HD;

    const int rw = 32 * warp;
    unsigned qa[2][8][4];
    #pragma unroll
    for (int h = 0; h < 2; h++) {
        int ra = rw + 16 * h + g;
        #pragma unroll
        for (int ks = 0; ks < 8; ks++) {
            qa[h][ks][0] = __float_as_uint(qg[(ra)     * HD + 8 * ks + tq]);
            qa[h][ks][1] = __float_as_uint(qg[(ra + 8) * HD + 8 * ks + tq]);
            qa[h][ks][2] = __float_as_uint(qg[(ra)     * HD + 8 * ks + tq + 4]);
            qa[h][ks][3] = __float_as_uint(qg[(ra + 8) * HD + 8 * ks + tq + 4]);
        }
    }

    float oacc[2][8][4];
    #pragma unroll
    for (int h = 0; h < 2; h++)
        #pragma unroll
        for (int n = 0; n < 8; n++)
            #pragma unroll
            for (int j = 0; j < 4; j++) oacc[h][n][j] = 0.0f;
    float ls[2][2] = {{0.f, 0.f}, {0.f, 0.f}};

    attn_load_async(Kb[0], Vb[0], kgb, vgb, tid);
    CP_COMMIT();

    const float C = 0.18033688f;   // 0.125 * log2(e)

    for (int tt = 0; tt < nt; tt++) {
        __syncthreads();
        if (tt + 1 < nt)
            attn_load_async(Kb[(tt + 1) & 1], Vb[(tt + 1) & 1],
                            kgb + (size_t)(tt + 1) * 64 * HD,
                            vgb + (size_t)(tt + 1) * 64 * HD, tid);
        CP_COMMIT();
        CP_WAIT1();
        __syncthreads();

        const unsigned* Ku = reinterpret_cast<const unsigned*>(Kb[tt & 1]);
        const unsigned* Vu = reinterpret_cast<const unsigned*>(Vb[tt & 1]);

        #pragma unroll
        for (int nb = 0; nb < 8; nb++) {
            // ---- S block: 4 independent mma chains (2 halves x even/odd kc) ----
            float cfa[2][4] = {{0.f,0.f,0.f,0.f},{0.f,0.f,0.f,0.f}};
            float cfb[2][4] = {{0.f,0.f,0.f,0.f},{0.f,0.f,0.f,0.f}};
            #pragma unroll
            for (int kc = 0; kc < 8; kc += 2) {
                unsigned b0 = Ku[(8 * nb + g) * PK + 8 * kc + tq];
                unsigned b1 = Ku[(8 * nb + g) * PK + 8 * kc + tq + 4];
                mma_tf32(cfa[0], qa[0][kc][0], qa[0][kc][1], qa[0][kc][2], qa[0][kc][3], b0, b1);
                mma_tf32(cfa[1], qa[1][kc][0], qa[1][kc][1], qa[1][kc][2], qa[1][kc][3], b0, b1);
                unsigned c0 = Ku[(8 * nb + g) * PK + 8 * (kc + 1) + tq];
                unsigned c1 = Ku[(8 * nb + g) * PK + 8 * (kc + 1) + tq + 4];
                mma_tf32(cfb[0], qa[0][kc + 1][0], qa[0][kc + 1][1], qa[0][kc + 1][2], qa[0][kc + 1][3], c0, c1);
                mma_tf32(cfb[1], qa[1][kc + 1][0], qa[1][kc + 1][1], qa[1][kc + 1][2], qa[1][kc + 1][3], c0, c1);
            }

            // ---- exp; C-fragment IS the PV A-fragment (no shuffles) ----
            unsigned pa[2][4];
            #pragma unroll
            for (int h = 0; h < 2; h++) {
                float e0 = ex2((cfa[h][0] + cfb[h][0]) * C);   // P[rA][phys 2tq]
                float e1 = ex2((cfa[h][1] + cfb[h][1]) * C);   // P[rA][phys 2tq+1]
                float e2 = ex2((cfa[h][2] + cfb[h][2]) * C);   // P[rB][phys 2tq]
                float e3 = ex2((cfa[h][3] + cfb[h][3]) * C);   // P[rB][phys 2tq+1]
                ls[h][0] += e0 + e1;
                ls[h][1] += e2 + e3;
                pa[h][0] = __float_as_uint(e0); // A[rA][log tq]
                pa[h][1] = __float_as_uint(e2); // A[rB][log tq]
                pa[h][2] = __float_as_uint(e1); // A[rA][log tq+4]
                pa[h][3] = __float_as_uint(e3); // A[rB][log tq+4]
            }

            // ---- O += P(:,nb) * V(nb,:) with sigma-permuted V rows ----
            const unsigned* vr0 = Vu + (8 * nb + 2 * tq)     * PV;  // log tq
            const unsigned* vr1 = Vu + (8 * nb + 2 * tq + 1) * PV;  // log tq+4
            #pragma unroll
            for (int nd = 0; nd < 8; nd++) {
                unsigned vb0 = vr0[8 * nd + g];
                unsigned vb1 = vr1[8 * nd + g];
                mma_tf32(oacc[0][nd], pa[0][0], pa[0][1], pa[0][2], pa[0][3], vb0, vb1);
                mma_tf32(oacc[1][nd], pa[1][0], pa[1][1], pa[1][2], pa[1][3], vb0, vb1);
            }
        }
    }

    // ---- epilogue: quad-reduce sums, write unnormalized partials ----
    const size_t rowbase = (size_t)z * BATCH * SEQ + (size_t)b * SEQ + q0;
    #pragma unroll
    for (int h = 0; h < 2; h++) {
        float l0 = ls[h][0], l1 = ls[h][1];
        l0 += __shfl_xor_sync(0xffffffffu, l0, 1);
        l0 += __shfl_xor_sync(0xffffffffu, l0, 2);
        l1 += __shfl_xor_sync(0xffffffffu, l1, 1);
        l1 += __shfl_xor_sync(0xffffffffu, l1, 2);
        int ra = rw + 16 * h + g;
        if (tq == 0) {
            g_lsum[rowbase + ra]     = l0;
            g_lsum[rowbase + ra + 8] = l1;
        }
        float* o0 = g_part + (rowbase + ra)     * HD;
        float* o1 = g_part + (rowbase + ra + 8) * HD;
        #pragma unroll
        for (int n = 0; n < 8; n++) {
            int cc = 8 * n + 2 * tq;
            *reinterpret_cast<float2*>(&o0[cc]) = make_float2(oacc[h][n][0], oacc[h][n][1]);
            *reinterpret_cast<float2*>(&o1[cc]) = make_float2(oacc[h][n][2], oacc[h][n][3]);
        }
    }
}

// ---------------------------------------------------------------------------
// Combine: out = (sum_z O_z) / (sum_z l_z)
// ---------------------------------------------------------------------------
__global__ __launch_bounds__(256) void combine_kernel(float* __restrict__ out)
{
    const int idx = blockIdx.x * blockDim.x + threadIdx.x;  // 262144 float4
    const int row = idx >> 4;
    const int c4  = idx & 15;
    const size_t stride = (size_t)BATCH * SEQ;

    float l = 0.0f;
    float4 o = make_float4(0.f, 0.f, 0.f, 0.f);
    #pragma unroll
    for (int zz = 0; zz < NSPLIT; zz++) {
        l += g_lsum[zz * stride + row];
        float4 p = *reinterpret_cast<const float4*>(
            &g_part[(zz * stride + row) * HD + c4 * 4]);
        o.x += p.x; o.y += p.y; o.z += p.z; o.w += p.w;
    }
    float inv = 1.0f / l;
    o.x *= inv; o.y *= inv; o.z *= inv; o.w *= inv;
    *reinterpret_cast<float4*>(&out[(size_t)row * HD + c4 * 4]) = o;
}

// ---------------------------------------------------------------------------
extern "C" void kernel_launch(void* const* d_in, const int* in_sizes, int n_in,
                              void* d_out, int out_size)
{
    const float* x  = (const float*)d_in[0];
    const float* WQ = (const float*)d_in[1];
    const float* WK = (const float*)d_in[2];
    const float* WV = (const float*)d_in[3];
    float* out = (float*)d_out;

    cudaFuncSetAttribute(proj_mma_kernel,
                         cudaFuncAttributeMaxDynamicSharedMemorySize,
                         PROJ_SMEM_BYTES);
    cudaFuncSetAttribute(attn_mma_kernel,
                         cudaFuncAttributeMaxDynamicSharedMemorySize,
                         ATTN_SMEM_BYTES);

    proj_mma_kernel<<<dim3(SEQ * BATCH / 128, 3), 128, PROJ_SMEM_BYTES>>>(x, WQ, WK, WV);
    attn_mma_kernel<<<dim3(SEQ / 128, BATCH, NSPLIT), 128, ATTN_SMEM_BYTES>>>();
    combine_kernel<<<(BATCH * SEQ * HD / 4) / 256, 256>>>(out);
}

// round 15
// speedup vs baseline: 1.0900x; 1.0900x over previous
#include <cuda_runtime.h>
#include <math.h>

#define BATCH 4
#define SEQ   4096
#define EMB   512
#define HD    64
#define NSPLIT 7

__device__ float g_q[BATCH * SEQ * HD];
__device__ float g_k[BATCH * SEQ * HD];   // column-interleaved within 8-blocks
__device__ float g_v[BATCH * SEQ * HD];   // row-pair-interleaved
__device__ float g_part[NSPLIT * BATCH * SEQ * HD];   // unnormalized O partials
__device__ float g_lsum[NSPLIT * BATCH * SEQ];        // exp-sum partials

// ---------------------------------------------------------------------------
__device__ __forceinline__ unsigned f2tf(float x) {
    unsigned r;
    asm("cvt.rna.tf32.f32 %0, %1;" : "=r"(r) : "f"(x));
    return r;
}
__device__ __forceinline__ float ex2(float x) {
    float r;
    asm("ex2.approx.ftz.f32 %0, %1;" : "=f"(r) : "f"(x));
    return r;
}

__device__ __forceinline__ void mma_tf32(float c[4],
                                         unsigned a0, unsigned a1,
                                         unsigned a2, unsigned a3,
                                         unsigned b0, unsigned b1) {
    asm volatile(
        "mma.sync.aligned.m16n8k8.row.col.f32.tf32.tf32.f32 "
        "{%0,%1,%2,%3}, {%4,%5,%6,%7}, {%8,%9}, {%0,%1,%2,%3};"
        : "+f"(c[0]), "+f"(c[1]), "+f"(c[2]), "+f"(c[3])
        : "r"(a0), "r"(a1), "r"(a2), "r"(a3), "r"(b0), "r"(b1));
}

#define CP_COMMIT() asm volatile("cp.async.commit_group;" ::: "memory")
#define CP_WAIT1()  asm volatile("cp.async.wait_group 1;" ::: "memory")

// ---------------------------------------------------------------------------
// tf32 projection (R10 mainloop — proven plateau). Output layouts:
//   Q: standard row-major [seq][64]
//   K: columns interleaved within each 8-block: logical j -> (j<4 ? 2j : 2(j-4)+1)
//   V: row pairs interleaved: addr = (row>>1)*128 + 2*col + (row&1)
// All values pre-rounded to tf32.
// ---------------------------------------------------------------------------
#define PPX 68
#define PROJ_SMEM_FLOATS (128 * PPX + 64 * PPX)
#define PROJ_SMEM_BYTES  (PROJ_SMEM_FLOATS * 4)
#define PNCHUNK (EMB / 64)   // 8

__global__ __launch_bounds__(128, 3) void proj_mma_kernel(
    const float* __restrict__ x,
    const float* __restrict__ WQ,
    const float* __restrict__ WK,
    const float* __restrict__ WV)
{
    extern __shared__ float psm[];
    float* Xs = psm;                // 128 x PPX (tf32 bits)
    float* Ws = psm + 128 * PPX;    // 64 x PPX (tf32 bits)

    const int y = blockIdx.y;
    const float* W;
    float* out;
    if (y == 0)      { W = WQ; out = g_q; }
    else if (y == 1) { W = WK; out = g_k; }
    else             { W = WV; out = g_v; }

    const int tid  = threadIdx.x;
    const int lane = tid & 31;
    const int warp = tid >> 5;
    const int g    = lane >> 2;
    const int tq   = lane & 3;
    const int bm   = blockIdx.x * 128;
    const int rw   = 32 * warp;

    const unsigned* Xu = reinterpret_cast<const unsigned*>(Xs);
    const unsigned* Wu = reinterpret_cast<const unsigned*>(Ws);

    float acc[2][8][4];
    #pragma unroll
    for (int h = 0; h < 2; h++)
        #pragma unroll
        for (int n = 0; n < 8; n++)
            #pragma unroll
            for (int j = 0; j < 4; j++) acc[h][n][j] = 0.0f;

    for (int c = 0; c < PNCHUNK; c++) {
        const int k0 = c * 64;
        __syncthreads();
        #pragma unroll
        for (int i = 0; i < 16; i++) {
            int f = tid + 128 * i;
            int row = f >> 4, c4 = f & 15;
            float4 v = *reinterpret_cast<const float4*>(
                &x[(size_t)(bm + row) * EMB + k0 + c4 * 4]);
            uint4 t = { f2tf(v.x), f2tf(v.y), f2tf(v.z), f2tf(v.w) };
            *reinterpret_cast<uint4*>(&Xs[row * PPX + c4 * 4]) = t;
        }
        #pragma unroll
        for (int i = 0; i < 8; i++) {
            int f = tid + 128 * i;
            int row = f >> 4, c4 = f & 15;
            float4 v = *reinterpret_cast<const float4*>(
                &W[(size_t)row * EMB + k0 + c4 * 4]);
            uint4 t = { f2tf(v.x), f2tf(v.y), f2tf(v.z), f2tf(v.w) };
            *reinterpret_cast<uint4*>(&Ws[row * PPX + c4 * 4]) = t;
        }
        __syncthreads();

        #pragma unroll
        for (int kc = 0; kc < 8; kc++) {
            unsigned xa[2][4];
            #pragma unroll
            for (int h = 0; h < 2; h++) {
                int ra = rw + 16 * h + g;
                xa[h][0] = Xu[(ra)     * PPX + 8 * kc + tq];
                xa[h][1] = Xu[(ra + 8) * PPX + 8 * kc + tq];
                xa[h][2] = Xu[(ra)     * PPX + 8 * kc + tq + 4];
                xa[h][3] = Xu[(ra + 8) * PPX + 8 * kc + tq + 4];
            }
            #pragma unroll
            for (int n = 0; n < 8; n++) {
                unsigned b0 = Wu[(8 * n + g) * PPX + 8 * kc + tq];
                unsigned b1 = Wu[(8 * n + g) * PPX + 8 * kc + tq + 4];
                mma_tf32(acc[0][n], xa[0][0], xa[0][1], xa[0][2], xa[0][3], b0, b1);
                mma_tf32(acc[1][n], xa[1][0], xa[1][1], xa[1][2], xa[1][3], b0, b1);
            }
        }
    }

    // ---- store pre-rounded tf32 in the consumer-optimal layout ----
    // K col permutation for this thread's two logical cols (2tq, 2tq+1):
    const int kp0 = (tq < 2) ? (4 * tq)     : (4 * tq - 7);
    const int kp1 = (tq < 2) ? (4 * tq + 2) : (4 * tq - 5);

    #pragma unroll
    for (int h = 0; h < 2; h++) {
        int ra = rw + 16 * h + g;
        #pragma unroll
        for (int rr = 0; rr < 2; rr++) {
            int rg = bm + ra + 8 * rr;
            #pragma unroll
            for (int n = 0; n < 8; n++) {
                float v0 = __uint_as_float(f2tf(acc[h][n][2 * rr]));
                float v1 = __uint_as_float(f2tf(acc[h][n][2 * rr + 1]));
                if (y == 0) {
                    *reinterpret_cast<float2*>(
                        &out[(size_t)rg * HD + 8 * n + 2 * tq]) = make_float2(v0, v1);
                } else if (y == 1) {
                    out[(size_t)rg * HD + 8 * n + kp0] = v0;
                    out[(size_t)rg * HD + 8 * n + kp1] = v1;
                } else {
                    size_t base = ((size_t)rg >> 1) * 128 + (rg & 1);
                    out[base + 2 * (8 * n + 2 * tq)]     = v0;
                    out[base + 2 * (8 * n + 2 * tq + 1)] = v1;
                }
            }
        }
    }
}

// ---------------------------------------------------------------------------
// Attention (R10 structure): tf32 mma, m32 warp tile, split-KV NSPLIT=7,
// cp.async double-buffered K/V, shuffle-free S->P.
// NEW: K/V fragment pairs are contiguous in the source layouts -> LDS.64
// (128 loads per warp-tile instead of 256). K pitch 72, V pair-pitch 136
// keep the 64-bit patterns bank-conflict-free.
// ---------------------------------------------------------------------------
#define PK   72
#define PVP  136
#define KBUF (64 * PK)
#define VBUF (32 * PVP)
#define ATTN_SMEM_BYTES ((2 * KBUF + 2 * VBUF) * 4)   // 71680 B

__device__ __forceinline__ void attn_load_async(float* Kd, float* Vd,
                                                const float* kg, const float* vg,
                                                int tid) {
    unsigned ka = (unsigned)__cvta_generic_to_shared(Kd);
    unsigned va = (unsigned)__cvta_generic_to_shared(Vd);
    // K: 64 rows x 16 chunks (16B), pitch PK
    #pragma unroll
    for (int i = 0; i < 8; i++) {
        int f = tid + 128 * i;
        int row = f >> 4, c4 = f & 15;
        asm volatile("cp.async.cg.shared.global [%0], [%1], 16;" ::
            "r"(ka + (unsigned)((row * PK + c4 * 4) * 4)),
            "l"(kg + row * HD + c4 * 4) : "memory");
    }
    // V: 32 pair-rows x 32 chunks (16B), pitch PVP
    #pragma unroll
    for (int i = 0; i < 8; i++) {
        int f = tid + 128 * i;
        int prow = f >> 5, c16 = f & 31;
        asm volatile("cp.async.cg.shared.global [%0], [%1], 16;" ::
            "r"(va + (unsigned)((prow * PVP + c16 * 4) * 4)),
            "l"(vg + prow * 128 + c16 * 4) : "memory");
    }
}

__global__ __launch_bounds__(128) void attn_mma_kernel()
{
    extern __shared__ float sm[];
    float* Kb[2] = { sm, sm + KBUF };
    float* Vb[2] = { sm + 2 * KBUF, sm + 2 * KBUF + VBUF };

    const int tid  = threadIdx.x;
    const int lane = tid & 31;
    const int warp = tid >> 5;
    const int g    = lane >> 2;
    const int tq   = lane & 3;
    const int b    = blockIdx.y;
    const int q0   = blockIdx.x * 128;
    const int z    = blockIdx.z;
    const int t_begin = (64 * z) / NSPLIT;
    const int t_end   = (64 * (z + 1)) / NSPLIT;
    const int nt      = t_end - t_begin;

    const float* qg  = g_q + ((size_t)b * SEQ + q0) * HD;
    const float* kgb = g_k + ((size_t)b * SEQ + (size_t)t_begin * 64) * HD;
    const float* vgb = g_v + ((size_t)b * SEQ + (size_t)t_begin * 64) * HD;

    const int rw = 32 * warp;
    unsigned qa[2][8][4];
    #pragma unroll
    for (int h = 0; h < 2; h++) {
        int ra = rw + 16 * h + g;
        #pragma unroll
        for (int ks = 0; ks < 8; ks++) {
            qa[h][ks][0] = __float_as_uint(qg[(ra)     * HD + 8 * ks + tq]);
            qa[h][ks][1] = __float_as_uint(qg[(ra + 8) * HD + 8 * ks + tq]);
            qa[h][ks][2] = __float_as_uint(qg[(ra)     * HD + 8 * ks + tq + 4]);
            qa[h][ks][3] = __float_as_uint(qg[(ra + 8) * HD + 8 * ks + tq + 4]);
        }
    }

    float oacc[2][8][4];
    #pragma unroll
    for (int h = 0; h < 2; h++)
        #pragma unroll
        for (int n = 0; n < 8; n++)
            #pragma unroll
            for (int j = 0; j < 4; j++) oacc[h][n][j] = 0.0f;
    float ls[2][2] = {{0.f, 0.f}, {0.f, 0.f}};

    attn_load_async(Kb[0], Vb[0], kgb, vgb, tid);
    CP_COMMIT();

    const float C = 0.18033688f;   // 0.125 * log2(e)

    for (int tt = 0; tt < nt; tt++) {
        __syncthreads();
        if (tt + 1 < nt)
            attn_load_async(Kb[(tt + 1) & 1], Vb[(tt + 1) & 1],
                            kgb + (size_t)(tt + 1) * 64 * HD,
                            vgb + (size_t)(tt + 1) * 64 * HD, tid);
        CP_COMMIT();
        CP_WAIT1();
        __syncthreads();

        const unsigned* Ku = reinterpret_cast<const unsigned*>(Kb[tt & 1]);
        const unsigned* Vu = reinterpret_cast<const unsigned*>(Vb[tt & 1]);

        #pragma unroll
        for (int nb = 0; nb < 8; nb++) {
            // ---- S block: K frag pairs via LDS.64 (interleaved layout) ----
            const unsigned* krow = Ku + (8 * nb + g) * PK + 2 * tq;
            float cf[2][4] = {{0.f,0.f,0.f,0.f},{0.f,0.f,0.f,0.f}};
            #pragma unroll
            for (int kc = 0; kc < 8; kc++) {
                uint2 kk = *reinterpret_cast<const uint2*>(&krow[8 * kc]);
                mma_tf32(cf[0], qa[0][kc][0], qa[0][kc][1], qa[0][kc][2], qa[0][kc][3], kk.x, kk.y);
                mma_tf32(cf[1], qa[1][kc][0], qa[1][kc][1], qa[1][kc][2], qa[1][kc][3], kk.x, kk.y);
            }

            // ---- exp; C-fragment IS the PV A-fragment (no shuffles) ----
            unsigned pa[2][4];
            #pragma unroll
            for (int h = 0; h < 2; h++) {
                float e0 = ex2(cf[h][0] * C);   // P[rA][phys 2tq]
                float e1 = ex2(cf[h][1] * C);   // P[rA][phys 2tq+1]
                float e2 = ex2(cf[h][2] * C);   // P[rB][phys 2tq]
                float e3 = ex2(cf[h][3] * C);   // P[rB][phys 2tq+1]
                ls[h][0] += e0 + e1;
                ls[h][1] += e2 + e3;
                pa[h][0] = __float_as_uint(e0); // A[rA][log tq]
                pa[h][1] = __float_as_uint(e2); // A[rB][log tq]
                pa[h][2] = __float_as_uint(e1); // A[rA][log tq+4]
                pa[h][3] = __float_as_uint(e3); // A[rB][log tq+4]
            }

            // ---- O += P(:,nb) * V(nb,:): V row pairs via LDS.64 ----
            const unsigned* vp = Vu + (4 * nb + tq) * PVP + 2 * g;
            #pragma unroll
            for (int nd = 0; nd < 8; nd++) {
                uint2 vv = *reinterpret_cast<const uint2*>(&vp[16 * nd]);
                mma_tf32(oacc[0][nd], pa[0][0], pa[0][1], pa[0][2], pa[0][3], vv.x, vv.y);
                mma_tf32(oacc[1][nd], pa[1][0], pa[1][1], pa[1][2], pa[1][3], vv.x, vv.y);
            }
        }
    }

    // ---- epilogue: quad-reduce sums, write unnormalized partials ----
    const size_t rowbase = (size_t)z * BATCH * SEQ + (size_t)b * SEQ + q0;
    #pragma unroll
    for (int h = 0; h < 2; h++) {
        float l0 = ls[h][0], l1 = ls[h][1];
        l0 += __shfl_xor_sync(0xffffffffu, l0, 1);
        l0 += __shfl_xor_sync(0xffffffffu, l0, 2);
        l1 += __shfl_xor_sync(0xffffffffu, l1, 1);
        l1 += __shfl_xor_sync(0xffffffffu, l1, 2);
        int ra = rw + 16 * h + g;
        if (tq == 0) {
            g_lsum[rowbase + ra]     = l0;
            g_lsum[rowbase + ra + 8] = l1;
        }
        float* o0 = g_part + (rowbase + ra)     * HD;
        float* o1 = g_part + (rowbase + ra + 8) * HD;
        #pragma unroll
        for (int n = 0; n < 8; n++) {
            int cc = 8 * n + 2 * tq;
            *reinterpret_cast<float2*>(&o0[cc]) = make_float2(oacc[h][n][0], oacc[h][n][1]);
            *reinterpret_cast<float2*>(&o1[cc]) = make_float2(oacc[h][n][2], oacc[h][n][3]);
        }
    }
}

// ---------------------------------------------------------------------------
// Combine: out = (sum_z O_z) / (sum_z l_z)
// ---------------------------------------------------------------------------
__global__ __launch_bounds__(256) void combine_kernel(float* __restrict__ out)
{
    const int idx = blockIdx.x * blockDim.x + threadIdx.x;  // 262144 float4
    const int row = idx >> 4;
    const int c4  = idx & 15;
    const size_t stride = (size_t)BATCH * SEQ;

    float l = 0.0f;
    float4 o = make_float4(0.f, 0.f, 0.f, 0.f);
    #pragma unroll
    for (int zz = 0; zz < NSPLIT; zz++) {
        l += g_lsum[zz * stride + row];
        float4 p = *reinterpret_cast<const float4*>(
            &g_part[(zz * stride + row) * HD + c4 * 4]);
        o.x += p.x; o.y += p.y; o.z += p.z; o.w += p.w;
    }
    float inv = 1.0f / l;
    o.x *= inv; o.y *= inv; o.z *= inv; o.w *= inv;
    *reinterpret_cast<float4*>(&out[(size_t)row * HD + c4 * 4]) = o;
}

// ---------------------------------------------------------------------------
extern "C" void kernel_launch(void* const* d_in, const int* in_sizes, int n_in,
                              void* d_out, int out_size)
{
    const float* x  = (const float*)d_in[0];
    const float* WQ = (const float*)d_in[1];
    const float* WK = (const float*)d_in[2];
    const float* WV = (const float*)d_in[3];
    float* out = (float*)d_out;

    cudaFuncSetAttribute(proj_mma_kernel,
                         cudaFuncAttributeMaxDynamicSharedMemorySize,
                         PROJ_SMEM_BYTES);
    cudaFuncSetAttribute(attn_mma_kernel,
                         cudaFuncAttributeMaxDynamicSharedMemorySize,
                         ATTN_SMEM_BYTES);

    proj_mma_kernel<<<dim3(SEQ * BATCH / 128, 3), 128, PROJ_SMEM_BYTES>>>(x, WQ, WK, WV);
    attn_mma_kernel<<<dim3(SEQ / 128, BATCH, NSPLIT), 128, ATTN_SMEM_BYTES>>>();
    combine_kernel<<<(BATCH * SEQ * HD / 4) / 256, 256>>>(out);
}

// round 16
// speedup vs baseline: 1.6236x; 1.4895x over previous
#include <cuda_runtime.h>
#include <math.h>

#define BATCH 4
#define SEQ   4096
#define EMB   512
#define HD    64
#define NSPLIT 7

// Q/K/V stored as fp16x2 words (32 words of 2 fp16 per 64-wide row)
__device__ unsigned g_q[BATCH * SEQ * 32];   // plain row-major words
__device__ unsigned g_k[BATCH * SEQ * 32];   // word-interleaved per 16-col block
__device__ unsigned g_v[BATCH * SEQ * 32];   // per-64-tile col-major, row-pair packed
__device__ float g_part[NSPLIT * BATCH * SEQ * HD];
__device__ float g_lsum[NSPLIT * BATCH * SEQ];

// ---------------------------------------------------------------------------
__device__ __forceinline__ unsigned f2tf(float x) {
    unsigned r;
    asm("cvt.rna.tf32.f32 %0, %1;" : "=r"(r) : "f"(x));
    return r;
}
__device__ __forceinline__ float ex2(float x) {
    float r;
    asm("ex2.approx.ftz.f32 %0, %1;" : "=f"(r) : "f"(x));
    return r;
}
// pack two f32 -> fp16x2 word (lo = first arg)
__device__ __forceinline__ unsigned h2(float lo, float hi) {
    unsigned r;
    asm("cvt.rn.f16x2.f32 %0, %1, %2;" : "=r"(r) : "f"(hi), "f"(lo));
    return r;
}

__device__ __forceinline__ void mma_tf32(float c[4],
                                         unsigned a0, unsigned a1,
                                         unsigned a2, unsigned a3,
                                         unsigned b0, unsigned b1) {
    asm volatile(
        "mma.sync.aligned.m16n8k8.row.col.f32.tf32.tf32.f32 "
        "{%0,%1,%2,%3}, {%4,%5,%6,%7}, {%8,%9}, {%0,%1,%2,%3};"
        : "+f"(c[0]), "+f"(c[1]), "+f"(c[2]), "+f"(c[3])
        : "r"(a0), "r"(a1), "r"(a2), "r"(a3), "r"(b0), "r"(b1));
}
__device__ __forceinline__ void mma_f16(float c[4], const unsigned a[4],
                                        unsigned b0, unsigned b1) {
    asm volatile(
        "mma.sync.aligned.m16n8k16.row.col.f32.f16.f16.f32 "
        "{%0,%1,%2,%3}, {%4,%5,%6,%7}, {%8,%9}, {%0,%1,%2,%3};"
        : "+f"(c[0]), "+f"(c[1]), "+f"(c[2]), "+f"(c[3])
        : "r"(a[0]), "r"(a[1]), "r"(a[2]), "r"(a[3]), "r"(b0), "r"(b1));
}

#define CP_COMMIT() asm volatile("cp.async.commit_group;" ::: "memory")
#define CP_WAIT1()  asm volatile("cp.async.wait_group 1;" ::: "memory")

// V word index for (even row, col): per-64-tile col-major, pair-interleaved
__device__ __forceinline__ size_t vword(int row_even, int col) {
    int bb = row_even >> 12;
    int ss = row_even & 4095;
    int t  = ss >> 6;
    int sp = (ss & 63) >> 1;
    int m  = sp >> 3;
    int j  = sp & 7;
    int phys = 8 * m + ((j < 4) ? 2 * j : 2 * (j - 4) + 1);
    return ((size_t)(bb * 64 + t) * 64 + col) * 32 + phys;
}

// ---------------------------------------------------------------------------
// tf32 projection (R10 mainloop — proven plateau). Epilogue emits fp16x2
// words in the attention-optimal layouts (Q plain / K interleaved / V packed).
// ---------------------------------------------------------------------------
#define PPX 68
#define PROJ_SMEM_FLOATS (128 * PPX + 64 * PPX)
#define PROJ_SMEM_BYTES  (PROJ_SMEM_FLOATS * 4)
#define PNCHUNK (EMB / 64)   // 8

__global__ __launch_bounds__(128, 3) void proj_mma_kernel(
    const float* __restrict__ x,
    const float* __restrict__ WQ,
    const float* __restrict__ WK,
    const float* __restrict__ WV)
{
    extern __shared__ float psm[];
    float* Xs = psm;                // 128 x PPX (tf32 bits)
    float* Ws = psm + 128 * PPX;    // 64 x PPX (tf32 bits)

    const int y = blockIdx.y;
    const float* W = (y == 0) ? WQ : (y == 1) ? WK : WV;

    const int tid  = threadIdx.x;
    const int lane = tid & 31;
    const int warp = tid >> 5;
    const int g    = lane >> 2;
    const int tq   = lane & 3;
    const int bm   = blockIdx.x * 128;
    const int rw   = 32 * warp;

    const unsigned* Xu = reinterpret_cast<const unsigned*>(Xs);
    const unsigned* Wu = reinterpret_cast<const unsigned*>(Ws);

    float acc[2][8][4];
    #pragma unroll
    for (int h = 0; h < 2; h++)
        #pragma unroll
        for (int n = 0; n < 8; n++)
            #pragma unroll
            for (int j = 0; j < 4; j++) acc[h][n][j] = 0.0f;

    for (int c = 0; c < PNCHUNK; c++) {
        const int k0 = c * 64;
        __syncthreads();
        #pragma unroll
        for (int i = 0; i < 16; i++) {
            int f = tid + 128 * i;
            int row = f >> 4, c4 = f & 15;
            float4 v = *reinterpret_cast<const float4*>(
                &x[(size_t)(bm + row) * EMB + k0 + c4 * 4]);
            uint4 t = { f2tf(v.x), f2tf(v.y), f2tf(v.z), f2tf(v.w) };
            *reinterpret_cast<uint4*>(&Xs[row * PPX + c4 * 4]) = t;
        }
        #pragma unroll
        for (int i = 0; i < 8; i++) {
            int f = tid + 128 * i;
            int row = f >> 4, c4 = f & 15;
            float4 v = *reinterpret_cast<const float4*>(
                &W[(size_t)row * EMB + k0 + c4 * 4]);
            uint4 t = { f2tf(v.x), f2tf(v.y), f2tf(v.z), f2tf(v.w) };
            *reinterpret_cast<uint4*>(&Ws[row * PPX + c4 * 4]) = t;
        }
        __syncthreads();

        #pragma unroll
        for (int kc = 0; kc < 8; kc++) {
            unsigned xa[2][4];
            #pragma unroll
            for (int h = 0; h < 2; h++) {
                int ra = rw + 16 * h + g;
                xa[h][0] = Xu[(ra)     * PPX + 8 * kc + tq];
                xa[h][1] = Xu[(ra + 8) * PPX + 8 * kc + tq];
                xa[h][2] = Xu[(ra)     * PPX + 8 * kc + tq + 4];
                xa[h][3] = Xu[(ra + 8) * PPX + 8 * kc + tq + 4];
            }
            #pragma unroll
            for (int n = 0; n < 8; n++) {
                unsigned b0 = Wu[(8 * n + g) * PPX + 8 * kc + tq];
                unsigned b1 = Wu[(8 * n + g) * PPX + 8 * kc + tq + 4];
                mma_tf32(acc[0][n], xa[0][0], xa[0][1], xa[0][2], xa[0][3], b0, b1);
                mma_tf32(acc[1][n], xa[1][0], xa[1][1], xa[1][2], xa[1][3], b0, b1);
            }
        }
    }

    // ---- epilogue: emit fp16x2 words in consumer-optimal layouts ----
    #pragma unroll
    for (int h = 0; h < 2; h++) {
        const int rAg = bm + rw + 16 * h + g;   // global row (this lane's rA)
        #pragma unroll
        for (int n = 0; n < 8; n++) {
            float c0 = acc[h][n][0], c1 = acc[h][n][1];
            float c2 = acc[h][n][2], c3 = acc[h][n][3];
            if (y == 0) {
                g_q[(size_t)rAg * 32 + 4 * n + tq]       = h2(c0, c1);
                g_q[(size_t)(rAg + 8) * 32 + 4 * n + tq] = h2(c2, c3);
            } else if (y == 1) {
                int widx = 8 * (n >> 1) + ((n & 1) ? 2 * tq + 1 : 2 * tq);
                g_k[(size_t)rAg * 32 + widx]       = h2(c0, c1);
                g_k[(size_t)(rAg + 8) * 32 + widx] = h2(c2, c3);
            } else {
                // V: pair rows (even,odd) packed; partner values via shfl
                float pc0 = __shfl_xor_sync(0xffffffffu, c0, 4);
                float pc1 = __shfl_xor_sync(0xffffffffu, c1, 4);
                float pc2 = __shfl_xor_sync(0xffffffffu, c2, 4);
                float pc3 = __shfl_xor_sync(0xffffffffu, c3, 4);
                int col = 8 * n + 2 * tq;
                if ((g & 1) == 0) {
                    size_t wi = vword(rAg, col);          // rows (rAg, rAg+1)
                    g_v[wi]      = h2(c0, pc0);
                    g_v[wi + 32] = h2(c1, pc1);           // col+1
                } else {
                    size_t wi = vword(rAg + 7, col);      // rows (rAg+7, rAg+8)
                    g_v[wi]      = h2(pc2, c2);
                    g_v[wi + 32] = h2(pc3, c3);
                }
            }
        }
    }
}

// ---------------------------------------------------------------------------
// Attention: fp16 m16n8k16 mma (2x tensor throughput vs tf32, same 10-bit
// mantissa), m32 warp tile, split-KV NSPLIT=7, cp.async double-buffered.
// C-fragment IS the PV A-fragment under k16 (no permutation at all).
// K pitch 40 words, V col-pitch 40 words: all LDS.64 conflict-free.
// ---------------------------------------------------------------------------
#define PKW  40
#define PVC  40
#define KBUFW (64 * PKW)
#define VBUFW (64 * PVC)
#define ATTN_SMEM_BYTES 59392   // 2*(KBUFW+VBUFW)*4 = 40960, padded to pin 3 CTAs/SM

__device__ __forceinline__ void attn_load_async(unsigned* Kd, unsigned* Vd,
                                                const unsigned* kg, const unsigned* vg,
                                                int tid) {
    unsigned ka = (unsigned)__cvta_generic_to_shared(Kd);
    unsigned va = (unsigned)__cvta_generic_to_shared(Vd);
    // K: 64 rows x 8 chunks(16B) ; V: 64 cols x 8 chunks(16B)
    #pragma unroll
    for (int i = 0; i < 4; i++) {
        int f = tid + 128 * i;
        int r = f >> 3, c = f & 7;
        asm volatile("cp.async.cg.shared.global [%0], [%1], 16;" ::
            "r"(ka + (unsigned)((r * PKW + c * 4) * 4)),
            "l"(kg + r * 32 + c * 4) : "memory");
        asm volatile("cp.async.cg.shared.global [%0], [%1], 16;" ::
            "r"(va + (unsigned)((r * PVC + c * 4) * 4)),
            "l"(vg + r * 32 + c * 4) : "memory");
    }
}

__global__ __launch_bounds__(128, 3) void attn_mma_kernel()
{
    extern __shared__ unsigned smw[];
    unsigned* Kb[2] = { smw, smw + KBUFW };
    unsigned* Vb[2] = { smw + 2 * KBUFW, smw + 2 * KBUFW + VBUFW };

    const int tid  = threadIdx.x;
    const int lane = tid & 31;
    const int warp = tid >> 5;
    const int g    = lane >> 2;
    const int tq   = lane & 3;
    const int b    = blockIdx.y;
    const int q0   = blockIdx.x * 128;
    const int z    = blockIdx.z;
    const int t_begin = (64 * z) / NSPLIT;
    const int t_end   = (64 * (z + 1)) / NSPLIT;
    const int nt      = t_end - t_begin;

    const unsigned* qw  = g_q + ((size_t)b * SEQ + q0) * 32;
    const unsigned* kgb = g_k + ((size_t)b * SEQ + (size_t)t_begin * 64) * 32;
    const unsigned* vgb = g_v + ((size_t)(b * 64 + t_begin)) * 2048;

    const int rw = 32 * warp;
    // Q A-fragments (fp16 k16): qa[h][kc][4], 32 regs
    unsigned qa[2][4][4];
    #pragma unroll
    for (int h = 0; h < 2; h++) {
        int rA = rw + 16 * h + g;
        int rB = rA + 8;
        #pragma unroll
        for (int kc = 0; kc < 4; kc++) {
            qa[h][kc][0] = qw[rA * 32 + 8 * kc + tq];
            qa[h][kc][1] = qw[rB * 32 + 8 * kc + tq];
            qa[h][kc][2] = qw[rA * 32 + 8 * kc + tq + 4];
            qa[h][kc][3] = qw[rB * 32 + 8 * kc + tq + 4];
        }
    }

    float oacc[2][8][4];
    #pragma unroll
    for (int h = 0; h < 2; h++)
        #pragma unroll
        for (int n = 0; n < 8; n++)
            #pragma unroll
            for (int j = 0; j < 4; j++) oacc[h][n][j] = 0.0f;
    float ls[2][2] = {{0.f, 0.f}, {0.f, 0.f}};

    attn_load_async(Kb[0], Vb[0], kgb, vgb, tid);
    CP_COMMIT();

    const float C = 0.18033688f;   // 0.125 * log2(e)

    for (int tt = 0; tt < nt; tt++) {
        __syncthreads();
        if (tt + 1 < nt)
            attn_load_async(Kb[(tt + 1) & 1], Vb[(tt + 1) & 1],
                            kgb + (size_t)(tt + 1) * 2048,
                            vgb + (size_t)(tt + 1) * 2048, tid);
        CP_COMMIT();
        CP_WAIT1();
        __syncthreads();

        const unsigned* Ku = Kb[tt & 1];
        const unsigned* Vu = Vb[tt & 1];

        #pragma unroll
        for (int m = 0; m < 4; m++) {     // nb pair (2m, 2m+1)
            // ---- S for both nb blocks (K B-frags via LDS.64) ----
            float cfA[2][4] = {{0.f,0.f,0.f,0.f},{0.f,0.f,0.f,0.f}};
            float cfB[2][4] = {{0.f,0.f,0.f,0.f},{0.f,0.f,0.f,0.f}};
            const unsigned* kr0 = Ku + (16 * m + g)     * PKW + 2 * tq;
            const unsigned* kr1 = Ku + (16 * m + 8 + g) * PKW + 2 * tq;
            #pragma unroll
            for (int kc = 0; kc < 4; kc++) {
                uint2 k0 = *reinterpret_cast<const uint2*>(&kr0[8 * kc]);
                mma_f16(cfA[0], qa[0][kc], k0.x, k0.y);
                mma_f16(cfA[1], qa[1][kc], k0.x, k0.y);
                uint2 k1 = *reinterpret_cast<const uint2*>(&kr1[8 * kc]);
                mma_f16(cfB[0], qa[0][kc], k1.x, k1.y);
                mma_f16(cfB[1], qa[1][kc], k1.x, k1.y);
            }

            // ---- exp + pack P A-fragments (k16 spans both nb blocks) ----
            unsigned pa[2][4];
            #pragma unroll
            for (int h = 0; h < 2; h++) {
                float eA0 = ex2(cfA[h][0] * C), eA1 = ex2(cfA[h][1] * C);
                float eA2 = ex2(cfA[h][2] * C), eA3 = ex2(cfA[h][3] * C);
                float eB0 = ex2(cfB[h][0] * C), eB1 = ex2(cfB[h][1] * C);
                float eB2 = ex2(cfB[h][2] * C), eB3 = ex2(cfB[h][3] * C);
                ls[h][0] += eA0 + eA1 + eB0 + eB1;
                ls[h][1] += eA2 + eA3 + eB2 + eB3;
                pa[h][0] = h2(eA0, eA1);   // row rA, cols 16m+2tq,+1
                pa[h][1] = h2(eA2, eA3);   // row rB
                pa[h][2] = h2(eB0, eB1);   // row rA, cols +8
                pa[h][3] = h2(eB2, eB3);   // row rB, cols +8
            }

            // ---- O += P(:,k16 m) * V (V B-frags via LDS.64) ----
            const unsigned* vbase = Vu + 8 * m + 2 * tq;
            #pragma unroll
            for (int nd = 0; nd < 8; nd++) {
                uint2 vv = *reinterpret_cast<const uint2*>(&vbase[(8 * nd + g) * PVC]);
                mma_f16(oacc[0][nd], pa[0], vv.x, vv.y);
                mma_f16(oacc[1][nd], pa[1], vv.x, vv.y);
            }
        }
    }

    // ---- epilogue: quad-reduce sums, write unnormalized partials ----
    const size_t rowbase = (size_t)z * BATCH * SEQ + (size_t)b * SEQ + q0;
    #pragma unroll
    for (int h = 0; h < 2; h++) {
        float l0 = ls[h][0], l1 = ls[h][1];
        l0 += __shfl_xor_sync(0xffffffffu, l0, 1);
        l0 += __shfl_xor_sync(0xffffffffu, l0, 2);
        l1 += __shfl_xor_sync(0xffffffffu, l1, 1);
        l1 += __shfl_xor_sync(0xffffffffu, l1, 2);
        int ra = rw + 16 * h + g;
        if (tq == 0) {
            g_lsum[rowbase + ra]     = l0;
            g_lsum[rowbase + ra + 8] = l1;
        }
        float* o0 = g_part + (rowbase + ra)     * HD;
        float* o1 = g_part + (rowbase + ra + 8) * HD;
        #pragma unroll
        for (int n = 0; n < 8; n++) {
            int cc = 8 * n + 2 * tq;
            *reinterpret_cast<float2*>(&o0[cc]) = make_float2(oacc[h][n][0], oacc[h][n][1]);
            *reinterpret_cast<float2*>(&o1[cc]) = make_float2(oacc[h][n][2], oacc[h][n][3]);
        }
    }
}

// ---------------------------------------------------------------------------
// Combine: out = (sum_z O_z) / (sum_z l_z)
// ---------------------------------------------------------------------------
__global__ __launch_bounds__(256) void combine_kernel(float* __restrict__ out)
{
    const int idx = blockIdx.x * blockDim.x + threadIdx.x;  // 262144 float4
    const int row = idx >> 4;
    const int c4  = idx & 15;
    const size_t stride = (size_t)BATCH * SEQ;

    float l = 0.0f;
    float4 o = make_float4(0.f, 0.f, 0.f, 0.f);
    #pragma unroll
    for (int zz = 0; zz < NSPLIT; zz++) {
        l += g_lsum[zz * stride + row];
        float4 p = *reinterpret_cast<const float4*>(
            &g_part[(zz * stride + row) * HD + c4 * 4]);
        o.x += p.x; o.y += p.y; o.z += p.z; o.w += p.w;
    }
    float inv = 1.0f / l;
    o.x *= inv; o.y *= inv; o.z *= inv; o.w *= inv;
    *reinterpret_cast<float4*>(&out[(size_t)row * HD + c4 * 4]) = o;
}

// ---------------------------------------------------------------------------
extern "C" void kernel_launch(void* const* d_in, const int* in_sizes, int n_in,
                              void* d_out, int out_size)
{
    const float* x  = (const float*)d_in[0];
    const float* WQ = (const float*)d_in[1];
    const float* WK = (const float*)d_in[2];
    const float* WV = (const float*)d_in[3];
    float* out = (float*)d_out;

    cudaFuncSetAttribute(proj_mma_kernel,
                         cudaFuncAttributeMaxDynamicSharedMemorySize,
                         PROJ_SMEM_BYTES);
    cudaFuncSetAttribute(attn_mma_kernel,
                         cudaFuncAttributeMaxDynamicSharedMemorySize,
                         ATTN_SMEM_BYTES);

    proj_mma_kernel<<<dim3(SEQ * BATCH / 128, 3), 128, PROJ_SMEM_BYTES>>>(x, WQ, WK, WV);
    attn_mma_kernel<<<dim3(SEQ / 128, BATCH, NSPLIT), 128, ATTN_SMEM_BYTES>>>();
    combine_kernel<<<(BATCH * SEQ * HD / 4) / 256, 256>>>(out);
}

// round 17
// speedup vs baseline: 1.6980x; 1.0459x over previous
#include <cuda_runtime.h>
#include <math.h>

#define BATCH 4
#define SEQ   4096
#define EMB   512
#define HD    64
#define NSPLIT 7

// Q/K/V stored as fp16x2 words (32 words of 2 fp16 per 64-wide row)
__device__ unsigned g_q[BATCH * SEQ * 32];   // plain row-major words
__device__ unsigned g_k[BATCH * SEQ * 32];   // word-interleaved per 16-col block
__device__ unsigned g_v[BATCH * SEQ * 32];   // per-64-tile col-major, row-pair packed
__device__ float g_part[NSPLIT * BATCH * SEQ * HD];
__device__ float g_lsum[NSPLIT * BATCH * SEQ];

// ---------------------------------------------------------------------------
__device__ __forceinline__ float ex2(float x) {
    float r;
    asm("ex2.approx.ftz.f32 %0, %1;" : "=f"(r) : "f"(x));
    return r;
}
// pack two f32 -> fp16x2 word (lo = first arg)
__device__ __forceinline__ unsigned h2(float lo, float hi) {
    unsigned r;
    asm("cvt.rn.f16x2.f32 %0, %1, %2;" : "=r"(r) : "f"(hi), "f"(lo));
    return r;
}

__device__ __forceinline__ void mma_f16(float c[4], const unsigned a[4],
                                        unsigned b0, unsigned b1) {
    asm volatile(
        "mma.sync.aligned.m16n8k16.row.col.f32.f16.f16.f32 "
        "{%0,%1,%2,%3}, {%4,%5,%6,%7}, {%8,%9}, {%0,%1,%2,%3};"
        : "+f"(c[0]), "+f"(c[1]), "+f"(c[2]), "+f"(c[3])
        : "r"(a[0]), "r"(a[1]), "r"(a[2]), "r"(a[3]), "r"(b0), "r"(b1));
}

#define CP_COMMIT() asm volatile("cp.async.commit_group;" ::: "memory")
#define CP_WAIT1()  asm volatile("cp.async.wait_group 1;" ::: "memory")

// V word index for (even row, col): per-64-tile col-major, pair-interleaved
__device__ __forceinline__ size_t vword(int row_even, int col) {
    int bb = row_even >> 12;
    int ss = row_even & 4095;
    int t  = ss >> 6;
    int sp = (ss & 63) >> 1;
    int m  = sp >> 3;
    int j  = sp & 7;
    int phys = 8 * m + ((j < 4) ? 2 * j : 2 * (j - 4) + 1);
    return ((size_t)(bb * 64 + t) * 64 + col) * 32 + phys;
}

// ---------------------------------------------------------------------------
// fp16 projection: C[16384,64] = X[16384,512] * W[64,512]^T.
// m16n8k16 mma (halved mma + fragment-LDS vs tf32 version), fp16x2 smem,
// convert-at-STS, m32 warp tiles over a 128-row X tile, single-buffered.
// Epilogue emits fp16x2 words in the attention-optimal layouts.
// ---------------------------------------------------------------------------
#define PW 36   // words per smem row (conflict-free: bank = 4g+tq)
#define PNCHUNK (EMB / 64)   // 8

__global__ __launch_bounds__(128, 3) void proj_mma_kernel(
    const float* __restrict__ x,
    const float* __restrict__ WQ,
    const float* __restrict__ WK,
    const float* __restrict__ WV)
{
    __shared__ unsigned Xw[128 * PW];
    __shared__ unsigned Ww[64 * PW];

    const int y = blockIdx.y;
    const float* W = (y == 0) ? WQ : (y == 1) ? WK : WV;

    const int tid  = threadIdx.x;
    const int lane = tid & 31;
    const int warp = tid >> 5;
    const int g    = lane >> 2;
    const int tq   = lane & 3;
    const int bm   = blockIdx.x * 128;
    const int rw   = 32 * warp;

    float acc[2][8][4];
    #pragma unroll
    for (int h = 0; h < 2; h++)
        #pragma unroll
        for (int n = 0; n < 8; n++)
            #pragma unroll
            for (int j = 0; j < 4; j++) acc[h][n][j] = 0.0f;

    for (int c = 0; c < PNCHUNK; c++) {
        const int k0 = c * 64;
        __syncthreads();
        // X tile: 128 rows x 16 float4 -> fp16x2 pairs
        #pragma unroll
        for (int i = 0; i < 16; i++) {
            int f = tid + 128 * i;
            int row = f >> 4, c4 = f & 15;
            float4 v = *reinterpret_cast<const float4*>(
                &x[(size_t)(bm + row) * EMB + k0 + c4 * 4]);
            uint2 t = { h2(v.x, v.y), h2(v.z, v.w) };
            *reinterpret_cast<uint2*>(&Xw[row * PW + 2 * c4]) = t;
        }
        // W tile: 64 rows x 16 float4
        #pragma unroll
        for (int i = 0; i < 8; i++) {
            int f = tid + 128 * i;
            int row = f >> 4, c4 = f & 15;
            float4 v = *reinterpret_cast<const float4*>(
                &W[(size_t)row * EMB + k0 + c4 * 4]);
            uint2 t = { h2(v.x, v.y), h2(v.z, v.w) };
            *reinterpret_cast<uint2*>(&Ww[row * PW + 2 * c4]) = t;
        }
        __syncthreads();

        #pragma unroll
        for (int kc = 0; kc < 4; kc++) {        // k16 steps over 64 cols
            unsigned xa[2][4];
            #pragma unroll
            for (int h = 0; h < 2; h++) {
                int ra = rw + 16 * h + g;
                xa[h][0] = Xw[(ra)     * PW + 8 * kc + tq];
                xa[h][1] = Xw[(ra + 8) * PW + 8 * kc + tq];
                xa[h][2] = Xw[(ra)     * PW + 8 * kc + tq + 4];
                xa[h][3] = Xw[(ra + 8) * PW + 8 * kc + tq + 4];
            }
            #pragma unroll
            for (int n = 0; n < 8; n++) {
                unsigned b0 = Ww[(8 * n + g) * PW + 8 * kc + tq];
                unsigned b1 = Ww[(8 * n + g) * PW + 8 * kc + tq + 4];
                mma_f16(acc[0][n], xa[0], b0, b1);
                mma_f16(acc[1][n], xa[1], b0, b1);
            }
        }
    }

    // ---- epilogue: emit fp16x2 words in consumer-optimal layouts ----
    #pragma unroll
    for (int h = 0; h < 2; h++) {
        const int rAg = bm + rw + 16 * h + g;   // global row (this lane's rA)
        #pragma unroll
        for (int n = 0; n < 8; n++) {
            float c0 = acc[h][n][0], c1 = acc[h][n][1];
            float c2 = acc[h][n][2], c3 = acc[h][n][3];
            if (y == 0) {
                g_q[(size_t)rAg * 32 + 4 * n + tq]       = h2(c0, c1);
                g_q[(size_t)(rAg + 8) * 32 + 4 * n + tq] = h2(c2, c3);
            } else if (y == 1) {
                int widx = 8 * (n >> 1) + ((n & 1) ? 2 * tq + 1 : 2 * tq);
                g_k[(size_t)rAg * 32 + widx]       = h2(c0, c1);
                g_k[(size_t)(rAg + 8) * 32 + widx] = h2(c2, c3);
            } else {
                // V: pair rows (even,odd) packed; partner values via shfl
                float pc0 = __shfl_xor_sync(0xffffffffu, c0, 4);
                float pc1 = __shfl_xor_sync(0xffffffffu, c1, 4);
                float pc2 = __shfl_xor_sync(0xffffffffu, c2, 4);
                float pc3 = __shfl_xor_sync(0xffffffffu, c3, 4);
                int col = 8 * n + 2 * tq;
                if ((g & 1) == 0) {
                    size_t wi = vword(rAg, col);          // rows (rAg, rAg+1)
                    g_v[wi]      = h2(c0, pc0);
                    g_v[wi + 32] = h2(c1, pc1);           // col+1
                } else {
                    size_t wi = vword(rAg + 7, col);      // rows (rAg+7, rAg+8)
                    g_v[wi]      = h2(pc2, c2);
                    g_v[wi + 32] = h2(pc3, c3);
                }
            }
        }
    }
}

// ---------------------------------------------------------------------------
// Attention: fp16 m16n8k16 mma, m32 warp tile, split-KV NSPLIT=7, cp.async
// double-buffered. C-fragment IS the PV A-fragment under k16.
// NEW: row exp-sums via an extra mma against an all-ones B fragment
// (exact fp32 tensor-core sums; no FADD chain, no epilogue shuffle-reduce).
// ---------------------------------------------------------------------------
#define PKW  40
#define PVC  40
#define KBUFW (64 * PKW)
#define VBUFW (64 * PVC)
#define ATTN_SMEM_BYTES 59392   // 40960 used, padded to pin 3 CTAs/SM

__device__ __forceinline__ void attn_load_async(unsigned* Kd, unsigned* Vd,
                                                const unsigned* kg, const unsigned* vg,
                                                int tid) {
    unsigned ka = (unsigned)__cvta_generic_to_shared(Kd);
    unsigned va = (unsigned)__cvta_generic_to_shared(Vd);
    #pragma unroll
    for (int i = 0; i < 4; i++) {
        int f = tid + 128 * i;
        int r = f >> 3, c = f & 7;
        asm volatile("cp.async.cg.shared.global [%0], [%1], 16;" ::
            "r"(ka + (unsigned)((r * PKW + c * 4) * 4)),
            "l"(kg + r * 32 + c * 4) : "memory");
        asm volatile("cp.async.cg.shared.global [%0], [%1], 16;" ::
            "r"(va + (unsigned)((r * PVC + c * 4) * 4)),
            "l"(vg + r * 32 + c * 4) : "memory");
    }
}

__global__ __launch_bounds__(128, 3) void attn_mma_kernel()
{
    extern __shared__ unsigned smw[];
    unsigned* Kb[2] = { smw, smw + KBUFW };
    unsigned* Vb[2] = { smw + 2 * KBUFW, smw + 2 * KBUFW + VBUFW };

    const int tid  = threadIdx.x;
    const int lane = tid & 31;
    const int warp = tid >> 5;
    const int g    = lane >> 2;
    const int tq   = lane & 3;
    const int b    = blockIdx.y;
    const int q0   = blockIdx.x * 128;
    const int z    = blockIdx.z;
    const int t_begin = (64 * z) / NSPLIT;
    const int t_end   = (64 * (z + 1)) / NSPLIT;
    const int nt      = t_end - t_begin;

    const unsigned* qw  = g_q + ((size_t)b * SEQ + q0) * 32;
    const unsigned* kgb = g_k + ((size_t)b * SEQ + (size_t)t_begin * 64) * 32;
    const unsigned* vgb = g_v + ((size_t)(b * 64 + t_begin)) * 2048;

    const int rw = 32 * warp;
    unsigned qa[2][4][4];
    #pragma unroll
    for (int h = 0; h < 2; h++) {
        int rA = rw + 16 * h + g;
        int rB = rA + 8;
        #pragma unroll
        for (int kc = 0; kc < 4; kc++) {
            qa[h][kc][0] = qw[rA * 32 + 8 * kc + tq];
            qa[h][kc][1] = qw[rB * 32 + 8 * kc + tq];
            qa[h][kc][2] = qw[rA * 32 + 8 * kc + tq + 4];
            qa[h][kc][3] = qw[rB * 32 + 8 * kc + tq + 4];
        }
    }

    float oacc[2][8][4];
    #pragma unroll
    for (int h = 0; h < 2; h++)
        #pragma unroll
        for (int n = 0; n < 8; n++)
            #pragma unroll
            for (int j = 0; j < 4; j++) oacc[h][n][j] = 0.0f;
    float lsacc[2][4] = {{0.f,0.f,0.f,0.f},{0.f,0.f,0.f,0.f}};
    const unsigned ONE2 = 0x3C003C00u;   // fp16 {1.0, 1.0}

    attn_load_async(Kb[0], Vb[0], kgb, vgb, tid);
    CP_COMMIT();

    const float C = 0.18033688f;   // 0.125 * log2(e)

    for (int tt = 0; tt < nt; tt++) {
        __syncthreads();
        if (tt + 1 < nt)
            attn_load_async(Kb[(tt + 1) & 1], Vb[(tt + 1) & 1],
                            kgb + (size_t)(tt + 1) * 2048,
                            vgb + (size_t)(tt + 1) * 2048, tid);
        CP_COMMIT();
        CP_WAIT1();
        __syncthreads();

        const unsigned* Ku = Kb[tt & 1];
        const unsigned* Vu = Vb[tt & 1];

        #pragma unroll
        for (int m = 0; m < 4; m++) {     // nb pair (2m, 2m+1)
            // ---- S for both nb blocks (K B-frags via LDS.64) ----
            float cfA[2][4] = {{0.f,0.f,0.f,0.f},{0.f,0.f,0.f,0.f}};
            float cfB[2][4] = {{0.f,0.f,0.f,0.f},{0.f,0.f,0.f,0.f}};
            const unsigned* kr0 = Ku + (16 * m + g)     * PKW + 2 * tq;
            const unsigned* kr1 = Ku + (16 * m + 8 + g) * PKW + 2 * tq;
            #pragma unroll
            for (int kc = 0; kc < 4; kc++) {
                uint2 k0 = *reinterpret_cast<const uint2*>(&kr0[8 * kc]);
                mma_f16(cfA[0], qa[0][kc], k0.x, k0.y);
                mma_f16(cfA[1], qa[1][kc], k0.x, k0.y);
                uint2 k1 = *reinterpret_cast<const uint2*>(&kr1[8 * kc]);
                mma_f16(cfB[0], qa[0][kc], k1.x, k1.y);
                mma_f16(cfB[1], qa[1][kc], k1.x, k1.y);
            }

            // ---- exp + pack P A-fragments; row sums via ones-mma ----
            unsigned pa[2][4];
            #pragma unroll
            for (int h = 0; h < 2; h++) {
                float eA0 = ex2(cfA[h][0] * C), eA1 = ex2(cfA[h][1] * C);
                float eA2 = ex2(cfA[h][2] * C), eA3 = ex2(cfA[h][3] * C);
                float eB0 = ex2(cfB[h][0] * C), eB1 = ex2(cfB[h][1] * C);
                float eB2 = ex2(cfB[h][2] * C), eB3 = ex2(cfB[h][3] * C);
                pa[h][0] = h2(eA0, eA1);   // row rA, cols 16m+2tq,+1
                pa[h][1] = h2(eA2, eA3);   // row rB
                pa[h][2] = h2(eB0, eB1);   // row rA, cols +8
                pa[h][3] = h2(eB2, eB3);   // row rB, cols +8
                mma_f16(lsacc[h], pa[h], ONE2, ONE2);  // exact fp32 row sums
            }

            // ---- O += P(:,k16 m) * V (V B-frags via LDS.64) ----
            const unsigned* vbase = Vu + 8 * m + 2 * tq;
            #pragma unroll
            for (int nd = 0; nd < 8; nd++) {
                uint2 vv = *reinterpret_cast<const uint2*>(&vbase[(8 * nd + g) * PVC]);
                mma_f16(oacc[0][nd], pa[0], vv.x, vv.y);
                mma_f16(oacc[1][nd], pa[1], vv.x, vv.y);
            }
        }
    }

    // ---- epilogue: every lane already holds full row sums ----
    const size_t rowbase = (size_t)z * BATCH * SEQ + (size_t)b * SEQ + q0;
    #pragma unroll
    for (int h = 0; h < 2; h++) {
        int ra = rw + 16 * h + g;
        if (tq == 0) {
            g_lsum[rowbase + ra]     = lsacc[h][0];   // row rA sum
            g_lsum[rowbase + ra + 8] = lsacc[h][2];   // row rB sum
        }
        float* o0 = g_part + (rowbase + ra)     * HD;
        float* o1 = g_part + (rowbase + ra + 8) * HD;
        #pragma unroll
        for (int n = 0; n < 8; n++) {
            int cc = 8 * n + 2 * tq;
            *reinterpret_cast<float2*>(&o0[cc]) = make_float2(oacc[h][n][0], oacc[h][n][1]);
            *reinterpret_cast<float2*>(&o1[cc]) = make_float2(oacc[h][n][2], oacc[h][n][3]);
        }
    }
}

// ---------------------------------------------------------------------------
// Combine: out = (sum_z O_z) / (sum_z l_z)
// ---------------------------------------------------------------------------
__global__ __launch_bounds__(256) void combine_kernel(float* __restrict__ out)
{
    const int idx = blockIdx.x * blockDim.x + threadIdx.x;  // 262144 float4
    const int row = idx >> 4;
    const int c4  = idx & 15;
    const size_t stride = (size_t)BATCH * SEQ;

    float l = 0.0f;
    float4 o = make_float4(0.f, 0.f, 0.f, 0.f);
    #pragma unroll
    for (int zz = 0; zz < NSPLIT; zz++) {
        l += g_lsum[zz * stride + row];
        float4 p = *reinterpret_cast<const float4*>(
            &g_part[(zz * stride + row) * HD + c4 * 4]);
        o.x += p.x; o.y += p.y; o.z += p.z; o.w += p.w;
    }
    float inv = 1.0f / l;
    o.x *= inv; o.y *= inv; o.z *= inv; o.w *= inv;
    *reinterpret_cast<float4*>(&out[(size_t)row * HD + c4 * 4]) = o;
}

// ---------------------------------------------------------------------------
extern "C" void kernel_launch(void* const* d_in, const int* in_sizes, int n_in,
                              void* d_out, int out_size)
{
    const float* x  = (const float*)d_in[0];
    const float* WQ = (const float*)d_in[1];
    const float* WK = (const float*)d_in[2];
    const float* WV = (const float*)d_in[3];
    float* out = (float*)d_out;

    cudaFuncSetAttribute(attn_mma_kernel,
                         cudaFuncAttributeMaxDynamicSharedMemorySize,
                         ATTN_SMEM_BYTES);

    proj_mma_kernel<<<dim3(SEQ * BATCH / 128, 3), 128>>>(x, WQ, WK, WV);
    attn_mma_kernel<<<dim3(SEQ / 128, BATCH, NSPLIT), 128, ATTN_SMEM_BYTES>>>();
    combine_kernel<<<(BATCH * SEQ * HD / 4) / 256, 256>>>(out);
}